// round 2
// baseline (speedup 1.0000x reference)
#include <cuda_runtime.h>
#include <math.h>

// Problem constants
#define BATCH 4
#define SEQ   2048
#define DIM   2048
#define BSD   ((long)BATCH * SEQ * DIM)   // 16,777,216 elems per tensor

// GEMM tiling
#define BM 128
#define BN 128
#define BK 16
#define TM 8
#define TN 8
#define NTHREADS 256

// Scratch (allocation-free: static device globals)
__device__ float g_Q[BSD];
__device__ float g_K[BSD];
__device__ float g_A[BSD];

// C[M,N] = alpha * A[M,K] * op(B),  op(B) = B[N,K]^T if TB else B[K,N]
// All row-major. M%128==0, N%128==0, K%16==0 assumed (holds here).
template <bool TB>
__global__ __launch_bounds__(NTHREADS) void gemm_kernel(
    const float* __restrict__ A, const float* __restrict__ B, float* __restrict__ C,
    int M, int N, int K,
    long aStride, long bStride, long cStride, float alpha)
{
    __shared__ float As[BK][BM];
    __shared__ float Bs[BK][BN];

    const int batch = blockIdx.z;
    A += (long)batch * aStride;
    B += (long)batch * bStride;
    C += (long)batch * cStride;

    const int tid = threadIdx.x;
    const int tx = tid & 15;        // 0..15 -> col group
    const int ty = tid >> 4;        // 0..15 -> row group
    const int rowBlock = blockIdx.y * BM;
    const int colBlock = blockIdx.x * BN;

    float acc[TM][TN];
#pragma unroll
    for (int i = 0; i < TM; i++)
#pragma unroll
        for (int j = 0; j < TN; j++) acc[i][j] = 0.0f;

    for (int k0 = 0; k0 < K; k0 += BK) {
        // ---- load A tile: rows [rowBlock, +128), cols [k0, +16) ----
        {
            const int r  = tid >> 2;       // 0..63
            const int c4 = (tid & 3) * 4;  // 0,4,8,12
#pragma unroll
            for (int it = 0; it < 2; it++) {
                const int row = r + it * 64;
                float4 v = *reinterpret_cast<const float4*>(
                    &A[(long)(rowBlock + row) * K + k0 + c4]);
                As[c4 + 0][row] = v.x;
                As[c4 + 1][row] = v.y;
                As[c4 + 2][row] = v.z;
                As[c4 + 3][row] = v.w;
            }
        }
        // ---- load B tile ----
        if (TB) {
            // B[N,K] row-major: rows [colBlock, +128), cols [k0, +16)
            const int r  = tid >> 2;
            const int c4 = (tid & 3) * 4;
#pragma unroll
            for (int it = 0; it < 2; it++) {
                const int row = r + it * 64;
                float4 v = *reinterpret_cast<const float4*>(
                    &B[(long)(colBlock + row) * K + k0 + c4]);
                Bs[c4 + 0][row] = v.x;
                Bs[c4 + 1][row] = v.y;
                Bs[c4 + 2][row] = v.z;
                Bs[c4 + 3][row] = v.w;
            }
        } else {
            // B[K,N] row-major: rows [k0, +16), cols [colBlock, +128)
            const int r  = tid >> 5;        // 0..7
            const int c4 = (tid & 31) * 4;  // 0..124
#pragma unroll
            for (int it = 0; it < 2; it++) {
                const int row = r + it * 8;
                float4 v = *reinterpret_cast<const float4*>(
                    &B[(long)(k0 + row) * N + colBlock + c4]);
                *reinterpret_cast<float4*>(&Bs[row][c4]) = v;
            }
        }
        __syncthreads();

        // ---- compute ----
#pragma unroll
        for (int kk = 0; kk < BK; kk++) {
            float ra[TM], rb[TN];
            float4 a0 = *reinterpret_cast<const float4*>(&As[kk][ty * TM + 0]);
            float4 a1 = *reinterpret_cast<const float4*>(&As[kk][ty * TM + 4]);
            ra[0] = a0.x; ra[1] = a0.y; ra[2] = a0.z; ra[3] = a0.w;
            ra[4] = a1.x; ra[5] = a1.y; ra[6] = a1.z; ra[7] = a1.w;
            float4 b0 = *reinterpret_cast<const float4*>(&Bs[kk][tx * TN + 0]);
            float4 b1 = *reinterpret_cast<const float4*>(&Bs[kk][tx * TN + 4]);
            rb[0] = b0.x; rb[1] = b0.y; rb[2] = b0.z; rb[3] = b0.w;
            rb[4] = b1.x; rb[5] = b1.y; rb[6] = b1.z; rb[7] = b1.w;
#pragma unroll
            for (int i = 0; i < TM; i++)
#pragma unroll
                for (int j = 0; j < TN; j++)
                    acc[i][j] = fmaf(ra[i], rb[j], acc[i][j]);
        }
        __syncthreads();
    }

    // ---- epilogue ----
#pragma unroll
    for (int i = 0; i < TM; i++) {
        const long cro = (long)(rowBlock + ty * TM + i) * N + colBlock + tx * TN;
        float4 o0, o1;
        o0.x = alpha * acc[i][0]; o0.y = alpha * acc[i][1];
        o0.z = alpha * acc[i][2]; o0.w = alpha * acc[i][3];
        o1.x = alpha * acc[i][4]; o1.y = alpha * acc[i][5];
        o1.z = alpha * acc[i][6]; o1.w = alpha * acc[i][7];
        *reinterpret_cast<float4*>(&C[cro + 0]) = o0;
        *reinterpret_cast<float4*>(&C[cro + 4]) = o1;
    }
}

// Row softmax over N=2048 columns; one block (256 threads) per row, in place.
// Warp-shuffle reductions (2 levels) instead of a smem tree.
__global__ __launch_bounds__(256) void softmax_rows(float* __restrict__ S)
{
    const long row = blockIdx.x;
    float* p = S + row * (long)DIM;
    const int tid  = threadIdx.x;
    const int lane = tid & 31;
    const int wid  = tid >> 5;

    __shared__ float red[8];

    float vals[8];
    float m = -INFINITY;
#pragma unroll
    for (int i = 0; i < 8; i++) {
        vals[i] = p[tid + i * 256];
        m = fmaxf(m, vals[i]);
    }
#pragma unroll
    for (int s = 16; s > 0; s >>= 1)
        m = fmaxf(m, __shfl_xor_sync(0xFFFFFFFFu, m, s));
    if (lane == 0) red[wid] = m;
    __syncthreads();
    m = red[lane & 7];
#pragma unroll
    for (int s = 4; s > 0; s >>= 1)
        m = fmaxf(m, __shfl_xor_sync(0xFFFFFFFFu, m, s));
    m = __shfl_sync(0xFFFFFFFFu, m, 0);

    float sum = 0.0f;
#pragma unroll
    for (int i = 0; i < 8; i++) {
        vals[i] = __expf(vals[i] - m);
        sum += vals[i];
    }
#pragma unroll
    for (int s = 16; s > 0; s >>= 1)
        sum += __shfl_xor_sync(0xFFFFFFFFu, sum, s);
    __syncthreads();          // protect red[] reuse
    if (lane == 0) red[wid] = sum;
    __syncthreads();
    sum = red[lane & 7];
#pragma unroll
    for (int s = 4; s > 0; s >>= 1)
        sum += __shfl_xor_sync(0xFFFFFFFFu, sum, s);
    sum = __shfl_sync(0xFFFFFFFFu, sum, 0);

    const float inv = 1.0f / sum;
#pragma unroll
    for (int i = 0; i < 8; i++) p[tid + i * 256] = vals[i] * inv;
}

extern "C" void kernel_launch(void* const* d_in, const int* in_sizes, int n_in,
                              void* d_out, int out_size)
{
    const float* xq = (const float*)d_in[0];
    const float* xk = (const float*)d_in[1];
    // d_in[2] = xv (dead), d_in[3] = attn_mask (dead)
    const float* Wq = (const float*)d_in[4];
    const float* Wk = (const float*)d_in[5];
    // d_in[6] = Wv (dead)
    float* out = (float*)d_out;

    float *pQ = nullptr, *pK = nullptr, *pA = nullptr;
    cudaGetSymbolAddress((void**)&pQ, g_Q);
    cudaGetSymbolAddress((void**)&pK, g_K);
    cudaGetSymbolAddress((void**)&pA, g_A);

    const float scale = 1.0f / sqrtf((float)DIM);

    // 1) Q = Xq * Wq^T   (M = B*S = 8192, N = K = 2048, single "batch")
    dim3 gridProj(DIM / BN, (BATCH * SEQ) / BM, 1);
    gemm_kernel<true><<<gridProj, NTHREADS>>>(xq, Wq, pQ,
        BATCH * SEQ, DIM, DIM, 0, 0, 0, 1.0f);

    // 2) K = Xk * Wk^T
    gemm_kernel<true><<<gridProj, NTHREADS>>>(xk, Wk, pK,
        BATCH * SEQ, DIM, DIM, 0, 0, 0, 1.0f);

    // 3) S = (Q * K^T) * scale   per batch
    dim3 gridAttn(SEQ / BN, SEQ / BM, BATCH);
    gemm_kernel<true><<<gridAttn, NTHREADS>>>(pQ, pK, pA,
        SEQ, SEQ, DIM, (long)SEQ * DIM, (long)SEQ * DIM, (long)SEQ * SEQ, scale);

    // 4) A = softmax_rows(S)   (B*S = 8192 rows of 2048)
    softmax_rows<<<BATCH * SEQ, 256>>>(pA);

    // 5) O = K * A   per batch (NN)
    gemm_kernel<false><<<gridAttn, NTHREADS>>>(pK, pA, out,
        SEQ, SEQ, DIM, (long)SEQ * DIM, (long)SEQ * SEQ, (long)SEQ * SEQ, 1.0f);
}

// round 4
// speedup vs baseline: 2.7847x; 2.7847x over previous
#include <cuda_runtime.h>
#include <math.h>
#include <stdint.h>

// Problem constants
#define BATCH 4
#define SEQ   2048
#define DIM   2048
#define BSD   ((long)BATCH * SEQ * DIM)

// GEMM tiling
#define BM 128
#define BN 128
#define BKK 32
#define NTHREADS 256
#define SPAD 36   // 32 + 4 pad: conflict-free frag LDS, 16B-aligned rows

// Scratch (allocation-free: static device globals)
__device__ float g_Q[BSD];
__device__ float g_K[BSD];
__device__ float g_A[BSD];

__device__ __forceinline__ uint32_t f2tf32(float x) {
    uint32_t u;
    asm("cvt.rna.tf32.f32 %0, %1;" : "=r"(u) : "f"(x));
    return u;
}

__device__ __forceinline__ void mma_tf32(float* d,
    uint32_t a0, uint32_t a1, uint32_t a2, uint32_t a3,
    uint32_t b0, uint32_t b1)
{
    asm volatile(
        "mma.sync.aligned.m16n8k8.row.col.f32.tf32.tf32.f32 "
        "{%0,%1,%2,%3}, {%4,%5,%6,%7}, {%8,%9}, {%0,%1,%2,%3};"
        : "+f"(d[0]), "+f"(d[1]), "+f"(d[2]), "+f"(d[3])
        : "r"(a0), "r"(a1), "r"(a2), "r"(a3), "r"(b0), "r"(b1));
}

// C[M,N] = alpha * A[M,K] * op(B),  op(B) = B[N,K]^T if TB else B[K,N]
// Row-major everywhere. M%128==0, N%128==0, K%32==0.
template <bool TB>
__global__ __launch_bounds__(NTHREADS) void gemm_tf32(
    const float* __restrict__ A, const float* __restrict__ B, float* __restrict__ C,
    int M, int N, int K,
    long aStride, long bStride, long cStride, float alpha)
{
    __shared__ uint32_t As[BM][SPAD];
    __shared__ uint32_t Bs[BN][SPAD];

    const int batch = blockIdx.z;
    A += (long)batch * aStride;
    B += (long)batch * bStride;
    C += (long)batch * cStride;

    const int tid  = threadIdx.x;
    const int lane = tid & 31;
    const int wid  = tid >> 5;
    const int wy   = wid & 3;   // 4 warps in M
    const int wx   = wid >> 2;  // 2 warps in N
    const int rowBlock = blockIdx.y * BM;
    const int colBlock = blockIdx.x * BN;

    // global-load mapping (both A-style tiles: 128 rows x 32 cols)
    const int lr  = tid >> 3;        // 0..31
    const int lc4 = (tid & 7) * 4;   // 0,4,...,28

    float acc[2][8][4];
#pragma unroll
    for (int mt = 0; mt < 2; mt++)
#pragma unroll
        for (int nt = 0; nt < 8; nt++)
#pragma unroll
            for (int i = 0; i < 4; i++) acc[mt][nt][i] = 0.0f;

    float4 pa[4], pb[4];

    // ---- prologue: prefetch k0 = 0 ----
#pragma unroll
    for (int it = 0; it < 4; it++) {
        const int row = lr + it * 32;
        pa[it] = *reinterpret_cast<const float4*>(&A[(long)(rowBlock + row) * K + lc4]);
        if (TB) {
            pb[it] = *reinterpret_cast<const float4*>(&B[(long)(colBlock + row) * K + lc4]);
        } else {
            pb[it] = *reinterpret_cast<const float4*>(&B[(long)lr * N + colBlock + lc4 + it * 32]);
        }
    }

    for (int k0 = 0; k0 < K; k0 += BKK) {
        // ---- STS current stage (with fp32 -> tf32 rna conversion) ----
#pragma unroll
        for (int it = 0; it < 4; it++) {
            const int row = lr + it * 32;
            uint4 va = make_uint4(f2tf32(pa[it].x), f2tf32(pa[it].y),
                                  f2tf32(pa[it].z), f2tf32(pa[it].w));
            *reinterpret_cast<uint4*>(&As[row][lc4]) = va;
            if (TB) {
                uint4 vb = make_uint4(f2tf32(pb[it].x), f2tf32(pb[it].y),
                                      f2tf32(pb[it].z), f2tf32(pb[it].w));
                *reinterpret_cast<uint4*>(&Bs[row][lc4]) = vb;
            } else {
                const int n0 = lc4 + it * 32;   // transpose store: Bs[n][k]
                Bs[n0 + 0][lr] = f2tf32(pb[it].x);
                Bs[n0 + 1][lr] = f2tf32(pb[it].y);
                Bs[n0 + 2][lr] = f2tf32(pb[it].z);
                Bs[n0 + 3][lr] = f2tf32(pb[it].w);
            }
        }
        __syncthreads();

        // ---- prefetch next stage ----
        if (k0 + BKK < K) {
            const int kn = k0 + BKK;
#pragma unroll
            for (int it = 0; it < 4; it++) {
                const int row = lr + it * 32;
                pa[it] = *reinterpret_cast<const float4*>(&A[(long)(rowBlock + row) * K + kn + lc4]);
                if (TB) {
                    pb[it] = *reinterpret_cast<const float4*>(&B[(long)(colBlock + row) * K + kn + lc4]);
                } else {
                    pb[it] = *reinterpret_cast<const float4*>(&B[(long)(kn + lr) * N + colBlock + lc4 + it * 32]);
                }
            }
        }

        // ---- compute: 4 k-steps of 8 ----
#pragma unroll
        for (int ks = 0; ks < 4; ks++) {
            const int kb = ks * 8;
            uint32_t bf[8][2];
#pragma unroll
            for (int nt = 0; nt < 8; nt++) {
                const int n = wx * 64 + nt * 8 + (lane >> 2);
                bf[nt][0] = Bs[n][kb + (lane & 3)];
                bf[nt][1] = Bs[n][kb + 4 + (lane & 3)];
            }
#pragma unroll
            for (int mt = 0; mt < 2; mt++) {
                const int r = wy * 32 + mt * 16 + (lane >> 2);
                const int c = kb + (lane & 3);
                uint32_t a0 = As[r][c];
                uint32_t a1 = As[r + 8][c];
                uint32_t a2 = As[r][c + 4];
                uint32_t a3 = As[r + 8][c + 4];
#pragma unroll
                for (int nt = 0; nt < 8; nt++)
                    mma_tf32(acc[mt][nt], a0, a1, a2, a3, bf[nt][0], bf[nt][1]);
            }
        }
        __syncthreads();
    }

    // ---- epilogue ----
#pragma unroll
    for (int mt = 0; mt < 2; mt++) {
#pragma unroll
        for (int nt = 0; nt < 8; nt++) {
            const int row = rowBlock + wy * 32 + mt * 16 + (lane >> 2);
            const int col = colBlock + wx * 64 + nt * 8 + (lane & 3) * 2;
            float2 v0 = make_float2(alpha * acc[mt][nt][0], alpha * acc[mt][nt][1]);
            float2 v1 = make_float2(alpha * acc[mt][nt][2], alpha * acc[mt][nt][3]);
            *reinterpret_cast<float2*>(&C[(long)row * N + col]) = v0;
            *reinterpret_cast<float2*>(&C[(long)(row + 8) * N + col]) = v1;
        }
    }
}

// Row softmax over N=2048 columns; one block (256 threads) per row, in place.
__global__ __launch_bounds__(256) void softmax_rows(float* __restrict__ S)
{
    const long row = blockIdx.x;
    float* p = S + row * (long)DIM;
    const int tid  = threadIdx.x;
    const int lane = tid & 31;
    const int wid  = tid >> 5;

    __shared__ float red[8];

    float vals[8];
    float m = -INFINITY;
#pragma unroll
    for (int i = 0; i < 8; i++) {
        vals[i] = p[tid + i * 256];
        m = fmaxf(m, vals[i]);
    }
#pragma unroll
    for (int s = 16; s > 0; s >>= 1)
        m = fmaxf(m, __shfl_xor_sync(0xFFFFFFFFu, m, s));
    if (lane == 0) red[wid] = m;
    __syncthreads();
    m = red[lane & 7];
#pragma unroll
    for (int s = 4; s > 0; s >>= 1)
        m = fmaxf(m, __shfl_xor_sync(0xFFFFFFFFu, m, s));
    m = __shfl_sync(0xFFFFFFFFu, m, 0);

    float sum = 0.0f;
#pragma unroll
    for (int i = 0; i < 8; i++) {
        vals[i] = __expf(vals[i] - m);
        sum += vals[i];
    }
#pragma unroll
    for (int s = 16; s > 0; s >>= 1)
        sum += __shfl_xor_sync(0xFFFFFFFFu, sum, s);
    __syncthreads();
    if (lane == 0) red[wid] = sum;
    __syncthreads();
    sum = red[lane & 7];
#pragma unroll
    for (int s = 4; s > 0; s >>= 1)
        sum += __shfl_xor_sync(0xFFFFFFFFu, sum, s);
    sum = __shfl_sync(0xFFFFFFFFu, sum, 0);

    const float inv = 1.0f / sum;
#pragma unroll
    for (int i = 0; i < 8; i++) p[tid + i * 256] = vals[i] * inv;
}

extern "C" void kernel_launch(void* const* d_in, const int* in_sizes, int n_in,
                              void* d_out, int out_size)
{
    const float* xq = (const float*)d_in[0];
    const float* xk = (const float*)d_in[1];
    // d_in[2] = xv (dead), d_in[3] = attn_mask (dead)
    const float* Wq = (const float*)d_in[4];
    const float* Wk = (const float*)d_in[5];
    // d_in[6] = Wv (dead)
    float* out = (float*)d_out;

    float *pQ = nullptr, *pK = nullptr, *pA = nullptr;
    cudaGetSymbolAddress((void**)&pQ, g_Q);
    cudaGetSymbolAddress((void**)&pK, g_K);
    cudaGetSymbolAddress((void**)&pA, g_A);

    const float scale = 1.0f / sqrtf((float)DIM);

    // 1) Q = Xq * Wq^T   (M = B*S = 8192, N = K = 2048)
    dim3 gridProj(DIM / BN, (BATCH * SEQ) / BM, 1);
    gemm_tf32<true><<<gridProj, NTHREADS>>>(xq, Wq, pQ,
        BATCH * SEQ, DIM, DIM, 0, 0, 0, 1.0f);

    // 2) K = Xk * Wk^T
    gemm_tf32<true><<<gridProj, NTHREADS>>>(xk, Wk, pK,
        BATCH * SEQ, DIM, DIM, 0, 0, 0, 1.0f);

    // 3) S = (Q * K^T) * scale   per batch
    dim3 gridAttn(SEQ / BN, SEQ / BM, BATCH);
    gemm_tf32<true><<<gridAttn, NTHREADS>>>(pQ, pK, pA,
        SEQ, SEQ, DIM, (long)SEQ * DIM, (long)SEQ * DIM, (long)SEQ * SEQ, scale);

    // 4) A = softmax_rows(S)
    softmax_rows<<<BATCH * SEQ, 256>>>(pA);

    // 5) O = K * A   per batch (NN)
    gemm_tf32<false><<<gridAttn, NTHREADS>>>(pK, pA, out,
        SEQ, SEQ, DIM, (long)SEQ * DIM, (long)SEQ * SEQ, (long)SEQ * SEQ, 1.0f);
}